// round 2
// baseline (speedup 1.0000x reference)
#include <cuda_runtime.h>
#include <cuda_bf16.h>
#include <cstdint>
#include <cstddef>

// Problem dims (fixed by the dataset)
#define BB 8
#define TC 2048
#define TQ 1024
#define DD 1024

// ---------------- scratch (allocation-free: __device__ globals) ----------------
__device__ __align__(256) float g_attn[(size_t)BB * TC * TQ];   // tf32-rounded softmax probs, 64 MiB
__device__ __align__(256) float g_qt[(size_t)BB * TQ * DD];     // tf32-rounded qencode,       32 MiB

// ---------------- helpers ----------------
__device__ __forceinline__ float tf32_rna(float x) {
    uint32_t o;
    asm("cvt.rna.tf32.f32 %0, %1;" : "=r"(o) : "f"(x));
    return __uint_as_float(o);
}
__device__ __forceinline__ uint32_t smem_u32(const void* p) {
    uint32_t a;
    asm("{ .reg .u64 t; cvta.to.shared.u64 t, %1; cvt.u32.u64 %0, t; }" : "=r"(a) : "l"(p));
    return a;
}
__device__ __forceinline__ void cp_async16(uint32_t s, const void* g) {
    asm volatile("cp.async.cg.shared.global [%0], [%1], 16;" :: "r"(s), "l"(g) : "memory");
}
__device__ __forceinline__ void cp_commit() {
    asm volatile("cp.async.commit_group;" ::: "memory");
}
template <int N>
__device__ __forceinline__ void cp_wait() {
    asm volatile("cp.async.wait_group %0;" :: "n"(N) : "memory");
}
__device__ __forceinline__ void mma_tf32(float& c0, float& c1, float& c2, float& c3,
                                         uint32_t a0, uint32_t a1, uint32_t a2, uint32_t a3,
                                         uint32_t b0, uint32_t b1) {
    asm volatile(
        "mma.sync.aligned.m16n8k8.row.col.f32.tf32.tf32.f32 "
        "{%0,%1,%2,%3}, {%4,%5,%6,%7}, {%8,%9}, {%0,%1,%2,%3};"
        : "+f"(c0), "+f"(c1), "+f"(c2), "+f"(c3)
        : "r"(a0), "r"(a1), "r"(a2), "r"(a3), "r"(b0), "r"(b1));
}

// ---------------- kernel 1: row softmax -> tf32-rounded probs ----------------
__global__ __launch_bounds__(256) void softmax_kernel(const float* __restrict__ sim) {
    int row = blockIdx.x;
    int t = threadIdx.x, wid = t >> 5, lid = t & 31;
    const float4* in = reinterpret_cast<const float4*>(sim + (size_t)row * TQ);
    float4* out = reinterpret_cast<float4*>(g_attn + (size_t)row * TQ);
    float4 v = in[t];

    __shared__ float red[8];
    float m = fmaxf(fmaxf(v.x, v.y), fmaxf(v.z, v.w));
    #pragma unroll
    for (int o = 16; o > 0; o >>= 1) m = fmaxf(m, __shfl_xor_sync(0xFFFFFFFFu, m, o));
    if (lid == 0) red[wid] = m;
    __syncthreads();
    float M = red[0];
    #pragma unroll
    for (int i = 1; i < 8; i++) M = fmaxf(M, red[i]);

    float e0 = __expf(v.x - M), e1 = __expf(v.y - M), e2 = __expf(v.z - M), e3 = __expf(v.w - M);
    float s = (e0 + e1) + (e2 + e3);
    #pragma unroll
    for (int o = 16; o > 0; o >>= 1) s += __shfl_xor_sync(0xFFFFFFFFu, s, o);
    __syncthreads();
    if (lid == 0) red[wid] = s;
    __syncthreads();
    float S = 0.f;
    #pragma unroll
    for (int i = 0; i < 8; i++) S += red[i];
    float inv = 1.0f / S;
    out[t] = make_float4(tf32_rna(e0 * inv), tf32_rna(e1 * inv),
                         tf32_rna(e2 * inv), tf32_rna(e3 * inv));
}

// ---------------- kernel 2: tf32-round qencode into scratch ----------------
__global__ __launch_bounds__(256) void round_b_kernel(const float* __restrict__ q) {
    size_t i = (size_t)blockIdx.x * 256 + threadIdx.x;     // float4 index
    float4 v = reinterpret_cast<const float4*>(q)[i];
    reinterpret_cast<float4*>(g_qt)[i] =
        make_float4(tf32_rna(v.x), tf32_rna(v.y), tf32_rna(v.z), tf32_rna(v.w));
}

// ---------------- kernel 3: TF32 mma.sync GEMM ----------------
// C[b, c, d] = sum_q A[b,c,q] * B[b,q,d]
// CTA tile 128x128, 8 warps (2x4), warp tile 64x32, KC=16, 4-stage cp.async pipeline.
static constexpr int KC = 16;
static constexpr int NCH = TQ / KC;            // 64 k-chunks
static constexpr int SA = 20;                  // A smem row stride (floats), conflict-free
static constexpr int SB = 136;                 // B smem row stride (floats), conflict-free
static constexpr int A_FLOATS = 128 * SA;      // 2560
static constexpr int B_FLOATS = KC * SB;       // 2176
static constexpr int STAGE_FLOATS = A_FLOATS + B_FLOATS;   // 4736 (18944 B)
static constexpr int STAGES = 4;
static constexpr int SMEM_BYTES = STAGES * STAGE_FLOATS * 4;  // 75776

__global__ __launch_bounds__(256, 1) void gemm_tf32_kernel(float* __restrict__ out) {
    extern __shared__ float smem[];
    const int tid = threadIdx.x;
    const int wid = tid >> 5, lane = tid & 31;
    const int g = lane >> 2, t = lane & 3;          // mma groupID / threadID-in-group
    const int wm = (wid & 1) * 64;                  // warp m offset within CTA tile
    const int wn = (wid >> 1) * 32;                 // warp n offset within CTA tile
    const int dtile = blockIdx.x, ctile = blockIdx.y, b = blockIdx.z;

    const float* Ag = g_attn + ((size_t)b * TC + (size_t)ctile * 128) * TQ;
    const float* Bg = g_qt + (size_t)b * TQ * DD + (size_t)dtile * 128;

    const uint32_t smem_base = smem_u32(smem);

    // per-thread fetch addressing (constant across chunks except the k offset)
    const int a_row = tid >> 2, a_ch = tid & 3;     // 2 iters of 64 rows
    const int b_row = tid >> 5, b_ch = tid & 31;    // 2 iters of 8 rows

    auto fetch = [&](int kc, int s) {
        uint32_t sa = smem_base + (uint32_t)(s * STAGE_FLOATS) * 4u;
        uint32_t sb = sa + (uint32_t)A_FLOATS * 4u;
        #pragma unroll
        for (int it = 0; it < 2; it++) {
            int row = a_row + it * 64;
            cp_async16(sa + (uint32_t)(row * SA + a_ch * 4) * 4u,
                       Ag + (size_t)row * TQ + kc * KC + a_ch * 4);
        }
        #pragma unroll
        for (int it = 0; it < 2; it++) {
            int row = b_row + it * 8;
            cp_async16(sb + (uint32_t)(row * SB + b_ch * 4) * 4u,
                       Bg + (size_t)(kc * KC + row) * DD + b_ch * 4);
        }
    };

    float acc[4][4][4];
    #pragma unroll
    for (int i = 0; i < 4; i++)
        #pragma unroll
        for (int j = 0; j < 4; j++)
            #pragma unroll
            for (int r = 0; r < 4; r++) acc[i][j][r] = 0.f;

    // prologue: prefetch 3 stages
    #pragma unroll
    for (int s = 0; s < STAGES - 1; s++) { fetch(s, s); cp_commit(); }

    for (int kc = 0; kc < NCH; kc++) {
        cp_wait<STAGES - 2>();
        __syncthreads();

        // prefetch next stage (overwrites the stage consumed STAGES-1 iters ago)
        if (kc + STAGES - 1 < NCH) fetch(kc + STAGES - 1, (kc + STAGES - 1) & (STAGES - 1));
        cp_commit();

        const float* sA = smem + (kc & (STAGES - 1)) * STAGE_FLOATS;
        const float* sB = sA + A_FLOATS;

        #pragma unroll
        for (int ks = 0; ks < 2; ks++) {
            const int k0 = ks * 8;
            uint32_t af[4][4], bf[4][2];
            #pragma unroll
            for (int i = 0; i < 4; i++) {
                int r0 = wm + i * 16 + g;
                af[i][0] = __float_as_uint(sA[r0 * SA + k0 + t]);
                af[i][1] = __float_as_uint(sA[(r0 + 8) * SA + k0 + t]);
                af[i][2] = __float_as_uint(sA[r0 * SA + k0 + t + 4]);
                af[i][3] = __float_as_uint(sA[(r0 + 8) * SA + k0 + t + 4]);
            }
            #pragma unroll
            for (int j = 0; j < 4; j++) {
                int n0 = wn + j * 8 + g;
                bf[j][0] = __float_as_uint(sB[(k0 + t) * SB + n0]);
                bf[j][1] = __float_as_uint(sB[(k0 + t + 4) * SB + n0]);
            }
            #pragma unroll
            for (int i = 0; i < 4; i++)
                #pragma unroll
                for (int j = 0; j < 4; j++)
                    mma_tf32(acc[i][j][0], acc[i][j][1], acc[i][j][2], acc[i][j][3],
                             af[i][0], af[i][1], af[i][2], af[i][3],
                             bf[j][0], bf[j][1]);
        }
    }
    cp_wait<0>();

    // epilogue: direct global stores (float2 per fragment pair)
    const size_t orow0 = (size_t)b * TC + ctile * 128 + wm + g;
    const int col0 = dtile * 128 + wn + t * 2;
    #pragma unroll
    for (int i = 0; i < 4; i++) {
        float* p0 = out + (orow0 + i * 16) * DD + col0;
        float* p1 = p0 + 8 * DD;
        #pragma unroll
        for (int j = 0; j < 4; j++) {
            *reinterpret_cast<float2*>(p0 + j * 8) = make_float2(acc[i][j][0], acc[i][j][1]);
            *reinterpret_cast<float2*>(p1 + j * 8) = make_float2(acc[i][j][2], acc[i][j][3]);
        }
    }
}

// ---------------- launcher ----------------
extern "C" void kernel_launch(void* const* d_in, const int* in_sizes, int n_in,
                              void* d_out, int out_size) {
    const float* sim  = (const float*)d_in[0];   // [8, 2048, 1024] fp32
    const float* qenc = (const float*)d_in[1];   // [8, 1024, 1024] fp32
    float* out = (float*)d_out;                  // [8, 2048, 1024] fp32

    cudaFuncSetAttribute(gemm_tf32_kernel, cudaFuncAttributeMaxDynamicSharedMemorySize, SMEM_BYTES);

    softmax_kernel<<<BB * TC, 256>>>(sim);
    round_b_kernel<<<(BB * TQ * DD) / (256 * 4), 256>>>(qenc);
    gemm_tf32_kernel<<<dim3(DD / 128, TC / 128, BB), 256, SMEM_BYTES>>>(out);
}

// round 4
// speedup vs baseline: 1.5148x; 1.5148x over previous
#include <cuda_runtime.h>
#include <cuda_fp16.h>
#include <cstdint>
#include <cstddef>

// Problem dims (fixed by the dataset)
#define BB 8
#define TC 2048
#define TQ 1024
#define DD 1024

// ---------------- scratch (allocation-free: __device__ globals) ----------------
__device__ __align__(256) __half g_attn[(size_t)BB * TC * TQ];  // fp16 softmax probs, 32 MiB
__device__ __align__(256) __half g_qt[(size_t)BB * DD * TQ];    // fp16 qencode^T [b][d][q], 16 MiB

// ---------------- helpers ----------------
__device__ __forceinline__ uint32_t smem_u32(const void* p) {
    uint32_t a;
    asm("{ .reg .u64 t; cvta.to.shared.u64 t, %1; cvt.u32.u64 %0, t; }" : "=r"(a) : "l"(p));
    return a;
}
__device__ __forceinline__ void cp_async16(uint32_t s, const void* g) {
    asm volatile("cp.async.cg.shared.global [%0], [%1], 16;" :: "r"(s), "l"(g) : "memory");
}
__device__ __forceinline__ void cp_commit() {
    asm volatile("cp.async.commit_group;" ::: "memory");
}
template <int N>
__device__ __forceinline__ void cp_wait() {
    asm volatile("cp.async.wait_group %0;" :: "n"(N) : "memory");
}
// m16n8k16 fp16 MMA, fp32 accumulate
__device__ __forceinline__ void mma_f16(float& c0, float& c1, float& c2, float& c3,
                                        uint32_t a0, uint32_t a1, uint32_t a2, uint32_t a3,
                                        uint32_t b0, uint32_t b1) {
    asm volatile(
        "mma.sync.aligned.m16n8k16.row.col.f32.f16.f16.f32 "
        "{%0,%1,%2,%3}, {%4,%5,%6,%7}, {%8,%9}, {%0,%1,%2,%3};"
        : "+f"(c0), "+f"(c1), "+f"(c2), "+f"(c3)
        : "r"(a0), "r"(a1), "r"(a2), "r"(a3), "r"(b0), "r"(b1));
}

// ---------------- kernel 1: row softmax -> fp16 probs ----------------
__global__ __launch_bounds__(256) void softmax_kernel(const float* __restrict__ sim) {
    int row = blockIdx.x;
    int t = threadIdx.x, wid = t >> 5, lid = t & 31;
    const float4* in = reinterpret_cast<const float4*>(sim + (size_t)row * TQ);
    float4 v = in[t];

    __shared__ float red[8];
    float m = fmaxf(fmaxf(v.x, v.y), fmaxf(v.z, v.w));
    #pragma unroll
    for (int o = 16; o > 0; o >>= 1) m = fmaxf(m, __shfl_xor_sync(0xFFFFFFFFu, m, o));
    if (lid == 0) red[wid] = m;
    __syncthreads();
    float M = red[0];
    #pragma unroll
    for (int i = 1; i < 8; i++) M = fmaxf(M, red[i]);

    float e0 = __expf(v.x - M), e1 = __expf(v.y - M), e2 = __expf(v.z - M), e3 = __expf(v.w - M);
    float s = (e0 + e1) + (e2 + e3);
    #pragma unroll
    for (int o = 16; o > 0; o >>= 1) s += __shfl_xor_sync(0xFFFFFFFFu, s, o);
    __syncthreads();
    if (lid == 0) red[wid] = s;
    __syncthreads();
    float S = 0.f;
    #pragma unroll
    for (int i = 0; i < 8; i++) S += red[i];
    float inv = 1.0f / S;

    __half2 h01 = __floats2half2_rn(e0 * inv, e1 * inv);
    __half2 h23 = __floats2half2_rn(e2 * inv, e3 * inv);
    uint2 pk;
    pk.x = *reinterpret_cast<uint32_t*>(&h01);
    pk.y = *reinterpret_cast<uint32_t*>(&h23);
    reinterpret_cast<uint2*>(g_attn + (size_t)row * TQ)[t] = pk;
}

// ---------------- kernel 2: transpose+convert qencode [b,q,d] fp32 -> g_qt [b,d,q] fp16 ----------------
__global__ __launch_bounds__(256) void transpose_kernel(const float* __restrict__ q) {
    __shared__ float tile[32][33];
    int dt = blockIdx.x, qt = blockIdx.y, b = blockIdx.z;
    int tx = threadIdx.x, ty = threadIdx.y;
    const float* src = q + (size_t)b * TQ * DD;
    #pragma unroll
    for (int i = 0; i < 4; i++) {
        int qq = qt * 32 + ty + i * 8;
        tile[ty + i * 8][tx] = src[(size_t)qq * DD + dt * 32 + tx];
    }
    __syncthreads();
    __half* dst = g_qt + (size_t)b * DD * TQ;
    #pragma unroll
    for (int i = 0; i < 4; i++) {
        int d2 = dt * 32 + ty + i * 8;
        dst[(size_t)d2 * TQ + qt * 32 + tx] = __float2half_rn(tile[tx][ty + i * 8]);
    }
}

// ---------------- kernel 3: FP16 mma.sync GEMM ----------------
// C[b, c, d] = sum_q A[b,c,q] * Bt[b,d,q]   (both operands K-major fp16)
// CTA tile 128x128, 8 warps (2x4), warp tile 64x32, KC=32 halves, 4-stage cp.async pipeline.
static constexpr int KC = 32;
static constexpr int NCH = TQ / KC;             // 32 k-chunks
static constexpr int SA = 40;                   // A smem row stride (halves) — conflict-free
static constexpr int SB = 40;                   // B smem row stride (halves) — conflict-free
static constexpr int A_HALVES = 128 * SA;       // 5120
static constexpr int B_HALVES = 128 * SB;       // 5120
static constexpr int STAGE_HALVES = A_HALVES + B_HALVES;      // 10240 (20480 B)
static constexpr int STAGES = 4;
static constexpr int SMEM_BYTES = STAGES * STAGE_HALVES * 2;  // 81920

__global__ __launch_bounds__(256, 1) void gemm_f16_kernel(float* __restrict__ out) {
    extern __shared__ __half smem[];
    const int tid = threadIdx.x;
    const int wid = tid >> 5, lane = tid & 31;
    const int g = lane >> 2, t = lane & 3;          // mma groupID / threadID-in-group
    const int wm = (wid & 1) * 64;                  // warp m offset within CTA tile
    const int wn = (wid >> 1) * 32;                 // warp n offset within CTA tile
    const int dtile = blockIdx.x, ctile = blockIdx.y, b = blockIdx.z;

    const __half* Ag = g_attn + ((size_t)b * TC + (size_t)ctile * 128) * TQ;
    const __half* Bg = g_qt + ((size_t)b * DD + (size_t)dtile * 128) * TQ;

    const uint32_t smem_base = smem_u32(smem);

    // fetch addressing: each thread copies 2x16B for A and 2x16B for B per stage
    // A/B tile: 128 rows x 32 halves (64 B = 4 x 16B chunks per row)
    const int f_row = tid >> 1;               // 0..127
    const int f_ch = (tid & 1) * 2;           // chunk 0 or 2 (each thread does ch, ch+1)

    auto fetch = [&](int kc, int s) {
        uint32_t sa = smem_base + (uint32_t)(s * STAGE_HALVES) * 2u;
        uint32_t sb = sa + (uint32_t)A_HALVES * 2u;
        const __half* ag = Ag + (size_t)f_row * TQ + kc * KC;
        const __half* bg = Bg + (size_t)f_row * TQ + kc * KC;
        #pragma unroll
        for (int c = 0; c < 2; c++) {
            int ch = f_ch + c;                                   // 16B chunk index 0..3
            cp_async16(sa + (uint32_t)(f_row * SA + ch * 8) * 2u, ag + ch * 8);
            cp_async16(sb + (uint32_t)(f_row * SB + ch * 8) * 2u, bg + ch * 8);
        }
    };

    float acc[4][4][4];
    #pragma unroll
    for (int i = 0; i < 4; i++)
        #pragma unroll
        for (int j = 0; j < 4; j++)
            #pragma unroll
            for (int r = 0; r < 4; r++) acc[i][j][r] = 0.f;

    #pragma unroll
    for (int s = 0; s < STAGES - 1; s++) { fetch(s, s); cp_commit(); }

    for (int kc = 0; kc < NCH; kc++) {
        cp_wait<STAGES - 2>();
        __syncthreads();

        if (kc + STAGES - 1 < NCH) fetch(kc + STAGES - 1, (kc + STAGES - 1) & (STAGES - 1));
        cp_commit();

        const __half* sA = smem + (kc & (STAGES - 1)) * STAGE_HALVES;
        const __half* sB = sA + A_HALVES;

        #pragma unroll
        for (int ks = 0; ks < 2; ks++) {
            const int k0 = ks * 16;
            uint32_t af[4][4], bf[4][2];
            #pragma unroll
            for (int i = 0; i < 4; i++) {
                int r0 = wm + i * 16 + g;
                af[i][0] = *reinterpret_cast<const uint32_t*>(sA + r0 * SA + k0 + 2 * t);
                af[i][1] = *reinterpret_cast<const uint32_t*>(sA + (r0 + 8) * SA + k0 + 2 * t);
                af[i][2] = *reinterpret_cast<const uint32_t*>(sA + r0 * SA + k0 + 2 * t + 8);
                af[i][3] = *reinterpret_cast<const uint32_t*>(sA + (r0 + 8) * SA + k0 + 2 * t + 8);
            }
            #pragma unroll
            for (int j = 0; j < 4; j++) {
                int n0 = wn + j * 8 + g;
                bf[j][0] = *reinterpret_cast<const uint32_t*>(sB + n0 * SB + k0 + 2 * t);
                bf[j][1] = *reinterpret_cast<const uint32_t*>(sB + n0 * SB + k0 + 2 * t + 8);
            }
            #pragma unroll
            for (int i = 0; i < 4; i++)
                #pragma unroll
                for (int j = 0; j < 4; j++)
                    mma_f16(acc[i][j][0], acc[i][j][1], acc[i][j][2], acc[i][j][3],
                            af[i][0], af[i][1], af[i][2], af[i][3],
                            bf[j][0], bf[j][1]);
        }
    }
    cp_wait<0>();

    // epilogue: direct global stores (float2 per fragment pair)
    const size_t orow0 = (size_t)b * TC + ctile * 128 + wm + g;
    const int col0 = dtile * 128 + wn + t * 2;
    #pragma unroll
    for (int i = 0; i < 4; i++) {
        float* p0 = out + (orow0 + i * 16) * DD + col0;
        float* p1 = p0 + 8 * DD;
        #pragma unroll
        for (int j = 0; j < 4; j++) {
            *reinterpret_cast<float2*>(p0 + j * 8) = make_float2(acc[i][j][0], acc[i][j][1]);
            *reinterpret_cast<float2*>(p1 + j * 8) = make_float2(acc[i][j][2], acc[i][j][3]);
        }
    }
}

// ---------------- launcher ----------------
extern "C" void kernel_launch(void* const* d_in, const int* in_sizes, int n_in,
                              void* d_out, int out_size) {
    const float* sim  = (const float*)d_in[0];   // [8, 2048, 1024] fp32
    const float* qenc = (const float*)d_in[1];   // [8, 1024, 1024] fp32
    float* out = (float*)d_out;                  // [8, 2048, 1024] fp32

    cudaFuncSetAttribute(gemm_f16_kernel, cudaFuncAttributeMaxDynamicSharedMemorySize, SMEM_BYTES);

    softmax_kernel<<<BB * TC, 256>>>(sim);
    transpose_kernel<<<dim3(DD / 32, TQ / 32, BB), dim3(32, 8)>>>(qenc);
    gemm_f16_kernel<<<dim3(DD / 128, TC / 128, BB), 256, SMEM_BYTES>>>(out);
}

// round 5
// speedup vs baseline: 1.9547x; 1.2904x over previous
#include <cuda_runtime.h>
#include <cuda_fp16.h>
#include <cstdint>
#include <cstddef>

// Problem dims (fixed by the dataset)
#define BB 8
#define TC 2048
#define TQ 1024
#define DD 1024

// ---------------- scratch (allocation-free: __device__ globals) ----------------
__device__ __align__(256) __half g_attn[(size_t)BB * TC * TQ];  // fp16 softmax probs, 32 MiB
__device__ __align__(256) __half g_qt[(size_t)BB * DD * TQ];    // fp16 qencode^T [b][d][q], 16 MiB

// ---------------- helpers ----------------
__device__ __forceinline__ uint32_t smem_u32(const void* p) {
    uint32_t a;
    asm("{ .reg .u64 t; cvta.to.shared.u64 t, %1; cvt.u32.u64 %0, t; }" : "=r"(a) : "l"(p));
    return a;
}
__device__ __forceinline__ void cp_async16(uint32_t s, const void* g) {
    asm volatile("cp.async.cg.shared.global [%0], [%1], 16;" :: "r"(s), "l"(g) : "memory");
}
__device__ __forceinline__ void cp_commit() {
    asm volatile("cp.async.commit_group;" ::: "memory");
}
template <int N>
__device__ __forceinline__ void cp_wait() {
    asm volatile("cp.async.wait_group %0;" :: "n"(N) : "memory");
}
__device__ __forceinline__ void ldsm_x4(uint32_t& r0, uint32_t& r1, uint32_t& r2, uint32_t& r3,
                                        uint32_t addr) {
    asm volatile("ldmatrix.sync.aligned.m8n8.x4.shared.b16 {%0,%1,%2,%3}, [%4];"
                 : "=r"(r0), "=r"(r1), "=r"(r2), "=r"(r3) : "r"(addr));
}
// m16n8k16 fp16 MMA, fp32 accumulate
__device__ __forceinline__ void mma_f16(float& c0, float& c1, float& c2, float& c3,
                                        uint32_t a0, uint32_t a1, uint32_t a2, uint32_t a3,
                                        uint32_t b0, uint32_t b1) {
    asm volatile(
        "mma.sync.aligned.m16n8k16.row.col.f32.f16.f16.f32 "
        "{%0,%1,%2,%3}, {%4,%5,%6,%7}, {%8,%9}, {%0,%1,%2,%3};"
        : "+f"(c0), "+f"(c1), "+f"(c2), "+f"(c3)
        : "r"(a0), "r"(a1), "r"(a2), "r"(a3), "r"(b0), "r"(b1));
}

// ---------------- kernel 1: row softmax -> fp16 probs (4 rows/block, MLP=4) ----------------
__global__ __launch_bounds__(256) void softmax_kernel(const float* __restrict__ sim) {
    const int tid = threadIdx.x;
    const int r = tid >> 6;            // row within block, 0..3
    const int s = tid & 63;            // 0..63 within row
    const int w = tid >> 5;            // warp 0..7 (two warps per row)
    const int lane = tid & 31;
    const size_t row = (size_t)blockIdx.x * 4 + r;

    const float4* in = reinterpret_cast<const float4*>(sim + row * TQ);
    float4 v[4];
    #pragma unroll
    for (int j = 0; j < 4; j++) v[j] = in[s + 64 * j];

    __shared__ float redm[8], reds[8];

    float m = -1e30f;
    #pragma unroll
    for (int j = 0; j < 4; j++)
        m = fmaxf(m, fmaxf(fmaxf(v[j].x, v[j].y), fmaxf(v[j].z, v[j].w)));
    #pragma unroll
    for (int o = 16; o > 0; o >>= 1) m = fmaxf(m, __shfl_xor_sync(0xFFFFFFFFu, m, o));
    if (lane == 0) redm[w] = m;
    __syncthreads();
    const float M = fmaxf(redm[w & ~1], redm[w | 1]);

    float e[4][4];
    float sum = 0.f;
    #pragma unroll
    for (int j = 0; j < 4; j++) {
        e[j][0] = __expf(v[j].x - M); e[j][1] = __expf(v[j].y - M);
        e[j][2] = __expf(v[j].z - M); e[j][3] = __expf(v[j].w - M);
        sum += (e[j][0] + e[j][1]) + (e[j][2] + e[j][3]);
    }
    #pragma unroll
    for (int o = 16; o > 0; o >>= 1) sum += __shfl_xor_sync(0xFFFFFFFFu, sum, o);
    if (lane == 0) reds[w] = sum;
    __syncthreads();
    const float inv = 1.0f / (reds[w & ~1] + reds[w | 1]);

    uint2* orow = reinterpret_cast<uint2*>(g_attn + row * TQ);
    #pragma unroll
    for (int j = 0; j < 4; j++) {
        __half2 h01 = __floats2half2_rn(e[j][0] * inv, e[j][1] * inv);
        __half2 h23 = __floats2half2_rn(e[j][2] * inv, e[j][3] * inv);
        uint2 pk;
        pk.x = *reinterpret_cast<uint32_t*>(&h01);
        pk.y = *reinterpret_cast<uint32_t*>(&h23);
        orow[s + 64 * j] = pk;
    }
}

// ---------------- kernel 2: transpose+convert qencode [b,q,d] fp32 -> g_qt [b,d,q] fp16 ----------------
__global__ __launch_bounds__(256) void transpose_kernel(const float* __restrict__ q) {
    __shared__ float tile[32][33];
    int dt = blockIdx.x, qt = blockIdx.y, b = blockIdx.z;
    int tx = threadIdx.x, ty = threadIdx.y;
    const float* src = q + (size_t)b * TQ * DD;
    #pragma unroll
    for (int i = 0; i < 4; i++) {
        int qq = qt * 32 + ty + i * 8;
        tile[ty + i * 8][tx] = src[(size_t)qq * DD + dt * 32 + tx];
    }
    __syncthreads();
    __half* dst = g_qt + (size_t)b * DD * TQ;
    #pragma unroll
    for (int i = 0; i < 4; i++) {
        int d2 = dt * 32 + ty + i * 8;
        dst[(size_t)d2 * TQ + qt * 32 + tx] = __float2half_rn(tile[tx][ty + i * 8]);
    }
}

// ---------------- kernel 3: FP16 mma.sync GEMM with ldmatrix ----------------
// C[b, c, d] = sum_q A[b,c,q] * Bt[b,d,q]   (both operands K-major fp16)
// CTA tile 128x128, 8 warps (2x4), warp tile 64x32, KC=64 halves, 3-stage cp.async pipeline.
static constexpr int KC = 64;
static constexpr int NCH = TQ / KC;              // 16 k-chunks
static constexpr int SROW = 72;                  // smem row stride (halves): conflict-free for ldmatrix
static constexpr int A_HALVES = 128 * SROW;      // 9216
static constexpr int A_BYTES = A_HALVES * 2;     // 18432
static constexpr int STAGE_BYTES = 2 * A_BYTES;  // 36864
static constexpr int STAGES = 3;
static constexpr int SMEM_BYTES = STAGES * STAGE_BYTES;  // 110592

__global__ __launch_bounds__(256, 1) void gemm_f16_kernel(float* __restrict__ out) {
    extern __shared__ __half smem[];
    const int tid = threadIdx.x;
    const int wid = tid >> 5, lane = tid & 31;
    const int g = lane >> 2, t = lane & 3;          // mma groupID / threadID-in-group
    const int wm = (wid & 1) * 64;                  // warp m offset within CTA tile
    const int wn = (wid >> 1) * 32;                 // warp n offset within CTA tile
    const int dtile = blockIdx.x, ctile = blockIdx.y, b = blockIdx.z;

    const __half* Ag = g_attn + ((size_t)b * TC + (size_t)ctile * 128) * TQ;
    const __half* Bg = g_qt + ((size_t)b * DD + (size_t)dtile * 128) * TQ;

    const uint32_t smem_base = smem_u32(smem);

    // cp.async addressing: tile = 128 rows x 64 halves = 1024 x 16B chunks; 4 per thread per operand
    const int f_row0 = tid >> 3;            // +32 per i
    const int f_ch = tid & 7;               // 16B chunk within row

    auto fetch = [&](int kc, int stg) {
        uint32_t sa = smem_base + (uint32_t)(stg * STAGE_BYTES);
        uint32_t sb = sa + (uint32_t)A_BYTES;
        #pragma unroll
        for (int i = 0; i < 4; i++) {
            int row = f_row0 + i * 32;
            uint32_t so = (uint32_t)(row * SROW + f_ch * 8) * 2u;
            const __half* ag = Ag + (size_t)row * TQ + kc * KC + f_ch * 8;
            const __half* bg = Bg + (size_t)row * TQ + kc * KC + f_ch * 8;
            cp_async16(sa + so, ag);
            cp_async16(sb + so, bg);
        }
    };

    // ldmatrix per-lane addressing (precomputed)
    const int a_row = wm + (lane & 15);             // + i*16
    const int a_col = (lane >> 4) * 8;              // + k0
    const int b_row = wn + (lane & 7) + (lane >> 4) * 8;  // + j2*16
    const int b_col = ((lane >> 3) & 1) * 8;        // + k0

    float acc[4][4][4];
    #pragma unroll
    for (int i = 0; i < 4; i++)
        #pragma unroll
        for (int j = 0; j < 4; j++)
            #pragma unroll
            for (int r = 0; r < 4; r++) acc[i][j][r] = 0.f;

    fetch(0, 0); cp_commit();
    fetch(1, 1); cp_commit();

    for (int kc = 0; kc < NCH; kc++) {
        cp_wait<STAGES - 2>();
        __syncthreads();

        if (kc + 2 < NCH) fetch(kc + 2, (kc + 2) % STAGES);
        cp_commit();

        const int stg = kc % STAGES;
        const uint32_t sA = smem_base + (uint32_t)(stg * STAGE_BYTES);
        const uint32_t sB = sA + (uint32_t)A_BYTES;

        #pragma unroll
        for (int ks = 0; ks < 4; ks++) {
            const int k0 = ks * 16;
            uint32_t af[4][4], bf[4][2];
            #pragma unroll
            for (int i = 0; i < 4; i++)
                ldsm_x4(af[i][0], af[i][1], af[i][2], af[i][3],
                        sA + (uint32_t)((a_row + i * 16) * SROW + k0 + a_col) * 2u);
            #pragma unroll
            for (int j2 = 0; j2 < 2; j2++)
                ldsm_x4(bf[j2 * 2][0], bf[j2 * 2][1], bf[j2 * 2 + 1][0], bf[j2 * 2 + 1][1],
                        sB + (uint32_t)((b_row + j2 * 16) * SROW + k0 + b_col) * 2u);
            #pragma unroll
            for (int i = 0; i < 4; i++)
                #pragma unroll
                for (int j = 0; j < 4; j++)
                    mma_f16(acc[i][j][0], acc[i][j][1], acc[i][j][2], acc[i][j][3],
                            af[i][0], af[i][1], af[i][2], af[i][3],
                            bf[j][0], bf[j][1]);
        }
    }
    cp_wait<0>();

    // epilogue: direct global stores (float2 per fragment pair)
    const size_t orow0 = (size_t)b * TC + ctile * 128 + wm + g;
    const int col0 = dtile * 128 + wn + t * 2;
    #pragma unroll
    for (int i = 0; i < 4; i++) {
        float* p0 = out + (orow0 + i * 16) * DD + col0;
        float* p1 = p0 + 8 * DD;
        #pragma unroll
        for (int j = 0; j < 4; j++) {
            *reinterpret_cast<float2*>(p0 + j * 8) = make_float2(acc[i][j][0], acc[i][j][1]);
            *reinterpret_cast<float2*>(p1 + j * 8) = make_float2(acc[i][j][2], acc[i][j][3]);
        }
    }
}

// ---------------- launcher ----------------
extern "C" void kernel_launch(void* const* d_in, const int* in_sizes, int n_in,
                              void* d_out, int out_size) {
    const float* sim  = (const float*)d_in[0];   // [8, 2048, 1024] fp32
    const float* qenc = (const float*)d_in[1];   // [8, 1024, 1024] fp32
    float* out = (float*)d_out;                  // [8, 2048, 1024] fp32

    cudaFuncSetAttribute(gemm_f16_kernel, cudaFuncAttributeMaxDynamicSharedMemorySize, SMEM_BYTES);

    softmax_kernel<<<BB * TC / 4, 256>>>(sim);
    transpose_kernel<<<dim3(DD / 32, TQ / 32, BB), dim3(32, 8)>>>(qenc);
    gemm_f16_kernel<<<dim3(DD / 128, TC / 128, BB), 256, SMEM_BYTES>>>(out);
}

// round 6
// speedup vs baseline: 2.2843x; 1.1686x over previous
#include <cuda_runtime.h>
#include <cuda_fp16.h>
#include <cstdint>
#include <cstddef>

// Problem dims (fixed by the dataset)
#define BB 8
#define TC 2048
#define TQ 1024
#define DD 1024

// ---------------- scratch (allocation-free: __device__ globals) ----------------
__device__ __align__(256) __half g_attn[(size_t)BB * TC * TQ];  // fp16 softmax probs, 32 MiB
__device__ __align__(256) __half g_qt[(size_t)BB * DD * TQ];    // fp16 qencode^T [b][d][q], 16 MiB

// ---------------- helpers ----------------
__device__ __forceinline__ uint32_t smem_u32(const void* p) {
    uint32_t a;
    asm("{ .reg .u64 t; cvta.to.shared.u64 t, %1; cvt.u32.u64 %0, t; }" : "=r"(a) : "l"(p));
    return a;
}
__device__ __forceinline__ void cp_async16(uint32_t s, const void* g) {
    asm volatile("cp.async.cg.shared.global [%0], [%1], 16;" :: "r"(s), "l"(g) : "memory");
}
__device__ __forceinline__ void cp_commit() {
    asm volatile("cp.async.commit_group;" ::: "memory");
}
template <int N>
__device__ __forceinline__ void cp_wait() {
    asm volatile("cp.async.wait_group %0;" :: "n"(N) : "memory");
}
__device__ __forceinline__ void ldsm_x4(uint32_t& r0, uint32_t& r1, uint32_t& r2, uint32_t& r3,
                                        uint32_t addr) {
    asm volatile("ldmatrix.sync.aligned.m8n8.x4.shared.b16 {%0,%1,%2,%3}, [%4];"
                 : "=r"(r0), "=r"(r1), "=r"(r2), "=r"(r3) : "r"(addr));
}
// m16n8k16 fp16 MMA, fp32 accumulate
__device__ __forceinline__ void mma_f16(float& c0, float& c1, float& c2, float& c3,
                                        uint32_t a0, uint32_t a1, uint32_t a2, uint32_t a3,
                                        uint32_t b0, uint32_t b1) {
    asm volatile(
        "mma.sync.aligned.m16n8k16.row.col.f32.f16.f16.f32 "
        "{%0,%1,%2,%3}, {%4,%5,%6,%7}, {%8,%9}, {%0,%1,%2,%3};"
        : "+f"(c0), "+f"(c1), "+f"(c2), "+f"(c3)
        : "r"(a0), "r"(a1), "r"(a2), "r"(a3), "r"(b0), "r"(b1));
}

// ---------------- kernel 1: row softmax -> fp16 probs (warp per row, no smem/sync) ----------------
__global__ __launch_bounds__(256) void softmax_kernel(const float* __restrict__ sim) {
    const int warp = threadIdx.x >> 5;
    const int lane = threadIdx.x & 31;
    const size_t row = (size_t)blockIdx.x * 8 + warp;

    const float4* in = reinterpret_cast<const float4*>(sim + row * TQ);
    float4 v[8];
    #pragma unroll
    for (int j = 0; j < 8; j++) v[j] = in[lane + 32 * j];

    float m = -1e30f;
    #pragma unroll
    for (int j = 0; j < 8; j++)
        m = fmaxf(m, fmaxf(fmaxf(v[j].x, v[j].y), fmaxf(v[j].z, v[j].w)));
    #pragma unroll
    for (int o = 16; o > 0; o >>= 1) m = fmaxf(m, __shfl_xor_sync(0xFFFFFFFFu, m, o));

    float sum = 0.f;
    #pragma unroll
    for (int j = 0; j < 8; j++) {
        v[j].x = __expf(v[j].x - m); v[j].y = __expf(v[j].y - m);
        v[j].z = __expf(v[j].z - m); v[j].w = __expf(v[j].w - m);
        sum += (v[j].x + v[j].y) + (v[j].z + v[j].w);
    }
    #pragma unroll
    for (int o = 16; o > 0; o >>= 1) sum += __shfl_xor_sync(0xFFFFFFFFu, sum, o);
    const float inv = 1.0f / sum;

    uint2* orow = reinterpret_cast<uint2*>(g_attn + row * TQ);
    #pragma unroll
    for (int j = 0; j < 8; j++) {
        __half2 h01 = __floats2half2_rn(v[j].x * inv, v[j].y * inv);
        __half2 h23 = __floats2half2_rn(v[j].z * inv, v[j].w * inv);
        uint2 pk;
        pk.x = *reinterpret_cast<uint32_t*>(&h01);
        pk.y = *reinterpret_cast<uint32_t*>(&h23);
        orow[lane + 32 * j] = pk;
    }
}

// ---------------- kernel 2: transpose+convert qencode [b,q,d] fp32 -> g_qt [b,d,q] fp16 ----------------
__global__ __launch_bounds__(256) void transpose_kernel(const float* __restrict__ q) {
    __shared__ float tile[32][33];
    int dt = blockIdx.x, qt = blockIdx.y, b = blockIdx.z;
    int tx = threadIdx.x, ty = threadIdx.y;
    const float* src = q + (size_t)b * TQ * DD;
    #pragma unroll
    for (int i = 0; i < 4; i++) {
        int qq = qt * 32 + ty + i * 8;
        tile[ty + i * 8][tx] = src[(size_t)qq * DD + dt * 32 + tx];
    }
    __syncthreads();
    __half* dst = g_qt + (size_t)b * DD * TQ;
    #pragma unroll
    for (int i = 0; i < 4; i++) {
        int d2 = dt * 32 + ty + i * 8;
        dst[(size_t)d2 * TQ + qt * 32 + tx] = __float2half_rn(tile[tx][ty + i * 8]);
    }
}

// ---------------- kernel 3: FP16 mma.sync GEMM with ldmatrix, 2 CTAs/SM ----------------
// C[b, c, d] = sum_q A[b,c,q] * Bt[b,d,q]   (both operands K-major fp16)
// CTA tile 128x128, 8 warps (2x4), warp tile 64x32, KC=64 halves, 3-stage cp.async pipeline.
static constexpr int KC = 64;
static constexpr int NCH = TQ / KC;              // 16 k-chunks
static constexpr int SROW = 72;                  // smem row stride (halves): conflict-free for ldmatrix
static constexpr int A_HALVES = 128 * SROW;      // 9216
static constexpr int A_BYTES = A_HALVES * 2;     // 18432
static constexpr int STAGE_BYTES = 2 * A_BYTES;  // 36864
static constexpr int STAGES = 3;
static constexpr int SMEM_BYTES = STAGES * STAGE_BYTES;  // 110592 (x2 CTAs = 221184 <= 228KB)

__global__ __launch_bounds__(256, 2) void gemm_f16_kernel(float* __restrict__ out) {
    extern __shared__ __half smem[];
    const int tid = threadIdx.x;
    const int wid = tid >> 5, lane = tid & 31;
    const int g = lane >> 2, t = lane & 3;          // mma groupID / threadID-in-group
    const int wm = (wid & 1) * 64;                  // warp m offset within CTA tile
    const int wn = (wid >> 1) * 32;                 // warp n offset within CTA tile
    const int dtile = blockIdx.x, ctile = blockIdx.y, b = blockIdx.z;

    const __half* Ag = g_attn + ((size_t)b * TC + (size_t)ctile * 128) * TQ;
    const __half* Bg = g_qt + ((size_t)b * DD + (size_t)dtile * 128) * TQ;

    const uint32_t smem_base = smem_u32(smem);

    // cp.async addressing: tile = 128 rows x 64 halves = 1024 x 16B chunks; 4 per thread per operand
    const int f_row0 = tid >> 3;            // +32 per i
    const int f_ch = tid & 7;               // 16B chunk within row

    auto fetch = [&](int kc, int stg) {
        uint32_t sa = smem_base + (uint32_t)(stg * STAGE_BYTES);
        uint32_t sb = sa + (uint32_t)A_BYTES;
        #pragma unroll
        for (int i = 0; i < 4; i++) {
            int row = f_row0 + i * 32;
            uint32_t so = (uint32_t)(row * SROW + f_ch * 8) * 2u;
            const __half* ag = Ag + (size_t)row * TQ + kc * KC + f_ch * 8;
            const __half* bg = Bg + (size_t)row * TQ + kc * KC + f_ch * 8;
            cp_async16(sa + so, ag);
            cp_async16(sb + so, bg);
        }
    };

    // ldmatrix per-lane addressing (precomputed)
    const int a_row = wm + (lane & 15);             // + i*16
    const int a_col = (lane >> 4) * 8;              // + k0
    const int b_row = wn + (lane & 7) + (lane >> 4) * 8;  // + j2*16
    const int b_col = ((lane >> 3) & 1) * 8;        // + k0

    float acc[4][4][4];
    #pragma unroll
    for (int i = 0; i < 4; i++)
        #pragma unroll
        for (int j = 0; j < 4; j++)
            #pragma unroll
            for (int r = 0; r < 4; r++) acc[i][j][r] = 0.f;

    fetch(0, 0); cp_commit();
    fetch(1, 1); cp_commit();

    for (int kc = 0; kc < NCH; kc++) {
        cp_wait<STAGES - 2>();
        __syncthreads();

        if (kc + 2 < NCH) fetch(kc + 2, (kc + 2) % STAGES);
        cp_commit();

        const int stg = kc % STAGES;
        const uint32_t sA = smem_base + (uint32_t)(stg * STAGE_BYTES);
        const uint32_t sB = sA + (uint32_t)A_BYTES;

        #pragma unroll
        for (int ks = 0; ks < 4; ks++) {
            const int k0 = ks * 16;
            uint32_t af[4][4], bf[4][2];
            #pragma unroll
            for (int i = 0; i < 4; i++)
                ldsm_x4(af[i][0], af[i][1], af[i][2], af[i][3],
                        sA + (uint32_t)((a_row + i * 16) * SROW + k0 + a_col) * 2u);
            #pragma unroll
            for (int j2 = 0; j2 < 2; j2++)
                ldsm_x4(bf[j2 * 2][0], bf[j2 * 2][1], bf[j2 * 2 + 1][0], bf[j2 * 2 + 1][1],
                        sB + (uint32_t)((b_row + j2 * 16) * SROW + k0 + b_col) * 2u);
            #pragma unroll
            for (int i = 0; i < 4; i++)
                #pragma unroll
                for (int j = 0; j < 4; j++)
                    mma_f16(acc[i][j][0], acc[i][j][1], acc[i][j][2], acc[i][j][3],
                            af[i][0], af[i][1], af[i][2], af[i][3],
                            bf[j][0], bf[j][1]);
        }
    }
    cp_wait<0>();

    // epilogue: direct global stores (float2 per fragment pair)
    const size_t orow0 = (size_t)b * TC + ctile * 128 + wm + g;
    const int col0 = dtile * 128 + wn + t * 2;
    #pragma unroll
    for (int i = 0; i < 4; i++) {
        float* p0 = out + (orow0 + i * 16) * DD + col0;
        float* p1 = p0 + 8 * DD;
        #pragma unroll
        for (int j = 0; j < 4; j++) {
            *reinterpret_cast<float2*>(p0 + j * 8) = make_float2(acc[i][j][0], acc[i][j][1]);
            *reinterpret_cast<float2*>(p1 + j * 8) = make_float2(acc[i][j][2], acc[i][j][3]);
        }
    }
}

// ---------------- launcher ----------------
extern "C" void kernel_launch(void* const* d_in, const int* in_sizes, int n_in,
                              void* d_out, int out_size) {
    const float* sim  = (const float*)d_in[0];   // [8, 2048, 1024] fp32
    const float* qenc = (const float*)d_in[1];   // [8, 1024, 1024] fp32
    float* out = (float*)d_out;                  // [8, 2048, 1024] fp32

    cudaFuncSetAttribute(gemm_f16_kernel, cudaFuncAttributeMaxDynamicSharedMemorySize, SMEM_BYTES);

    softmax_kernel<<<BB * TC / 8, 256>>>(sim);
    transpose_kernel<<<dim3(DD / 32, TQ / 32, BB), dim3(32, 8)>>>(qenc);
    gemm_f16_kernel<<<dim3(DD / 128, TC / 128, BB), 256, SMEM_BYTES>>>(out);
}